// round 12
// baseline (speedup 1.0000x reference)
#include <cuda_runtime.h>
#include <cuda_fp16.h>
#include <cstdint>

// fp16 mma.sync attention, single compute pass + streaming normalize tail.
// Compute pass: QK -> u = exp(s/8) (unnormalized) -> rowsum; u packed fp16 and
// stored to __device__ scratch in per-thread fragment layout (coalesced);
// PV accumulates UNNORMALIZED context (scaled by 1/rowsum at the end).
// Normalize tail: each thread re-reads its own u chunks, scales by inv,
// quad-merges and streams fp32 scores with STG.128. No recomputed QK/exp.
// K/V pre-converted fp32->fp16 by cvt kernel; Q converted in-kernel prologue.

namespace {
constexpr int Bc = 8, Hc = 12, Sc = 1024, Dc = 64;
constexpr int QT = 128, KT = 64, NKT = Sc / KT;
constexpr long long SCORE_ELEMS = (long long)Bc * Hc * Sc * Sc;
constexpr float EC = 0.18033688011112042f;  // log2(e) / 8
constexpr int NELEM = Bc * Hc * Sc * Dc;
constexpr int N4 = NELEM / 4;
constexpr int NT = 128;
constexpr int NCTA = (Sc / QT) * Bc * Hc;   // 768

constexpr int OFF_Q = 0;
constexpr int OFF_ST = 16384;               // 3 stages x (K 8KB + V 8KB)
constexpr int STAGE_SZ = 16384, V_IN_STAGE = 8192;
constexpr int SMEM_TOTAL = OFF_ST + 3 * STAGE_SZ;  // 65536

__device__ __forceinline__ uint32_t swz(uint32_t off) { return off ^ ((off >> 3) & 0x70); }
__device__ __forceinline__ uint32_t smem_u32(const void* p) {
    uint32_t a;
    asm("{ .reg .u64 t; cvta.to.shared.u64 t, %1; cvt.u32.u64 %0, t; }" : "=r"(a) : "l"(p));
    return a;
}
__device__ __forceinline__ uint32_t h2u(__half2 h) { return *reinterpret_cast<uint32_t*>(&h); }
__device__ __forceinline__ __half2 u2h(uint32_t u) { return *reinterpret_cast<__half2*>(&u); }
__device__ __forceinline__ float ex2(float x) {
    float r;
    asm("ex2.approx.f32 %0, %1;" : "=f"(r) : "f"(x));
    return r;
}
__device__ __forceinline__ void ldsm4(uint32_t r[4], uint32_t a) {
    asm volatile("ldmatrix.sync.aligned.m8n8.x4.shared.b16 {%0,%1,%2,%3}, [%4];"
                 : "=r"(r[0]), "=r"(r[1]), "=r"(r[2]), "=r"(r[3]) : "r"(a));
}
__device__ __forceinline__ void ldsm4t(uint32_t r[4], uint32_t a) {
    asm volatile("ldmatrix.sync.aligned.m8n8.x4.trans.shared.b16 {%0,%1,%2,%3}, [%4];"
                 : "=r"(r[0]), "=r"(r[1]), "=r"(r[2]), "=r"(r[3]) : "r"(a));
}
__device__ __forceinline__ void mma16816(float c[4], const uint32_t a[4],
                                         uint32_t b0, uint32_t b1) {
    asm volatile(
        "mma.sync.aligned.m16n8k16.row.col.f32.f16.f16.f32 "
        "{%0,%1,%2,%3}, {%4,%5,%6,%7}, {%8,%9}, {%0,%1,%2,%3};"
        : "+f"(c[0]), "+f"(c[1]), "+f"(c[2]), "+f"(c[3])
        : "r"(a[0]), "r"(a[1]), "r"(a[2]), "r"(a[3]), "r"(b0), "r"(b1));
}
__device__ __forceinline__ void cpa16(uint32_t d, const void* s) {
    asm volatile("cp.async.cg.shared.global [%0], [%1], 16;" :: "r"(d), "l"(s) : "memory");
}
#define CP_COMMIT() asm volatile("cp.async.commit_group;" ::: "memory")
#define CP_WAIT1()  asm volatile("cp.async.wait_group 1;" ::: "memory")

// Merge this lane's (e0,e1) [cols 2m,2m+1] and (o0,o1) [cols 2m+8,2m+9] with
// partner lane (xor 1) into one float4 of 4 contiguous columns.
__device__ __forceinline__ float4 quad_merge(bool odd, float e0, float e1,
                                             float o0, float o1) {
    float sx = odd ? e0 : o0, sy = odd ? e1 : o1;
    float rx = __shfl_xor_sync(0xffffffffu, sx, 1);
    float ry = __shfl_xor_sync(0xffffffffu, sy, 1);
    return odd ? make_float4(rx, ry, o0, o1) : make_float4(e0, e1, rx, ry);
}
}  // namespace

__device__ __align__(16) __half g_kh[NELEM];
__device__ __align__(16) __half g_vh[NELEM];
// u scratch: [cta][kt][tid][8] uint4 (fragment-packed fp16), 201MB
__device__ uint4 g_us[(size_t)NCTA * NKT * NT * 8];

__global__ __launch_bounds__(256)
void cvt_kernel(const float4* __restrict__ k, const float4* __restrict__ v) {
    int i = blockIdx.x * blockDim.x + threadIdx.x;
    const float4* src;
    uint2* dst;
    int j;
    if (i < N4) { src = k; dst = reinterpret_cast<uint2*>(g_kh); j = i; }
    else        { src = v; dst = reinterpret_cast<uint2*>(g_vh); j = i - N4; }
    float4 x = src[j];
    dst[j] = make_uint2(h2u(__floats2half2_rn(x.x, x.y)), h2u(__floats2half2_rn(x.z, x.w)));
}

namespace {
__device__ __forceinline__ void load_tile64(uint32_t dstBase, const __half* gsrc, int tid) {
    #pragma unroll
    for (int i = 0; i < 4; i++) {
        int c = tid + i * NT;
        int r = c >> 3, ch = c & 7;
        cpa16(dstBase + swz((uint32_t)(r * 128 + ch * 16)), gsrc + r * 64 + ch * 8);
    }
}
__device__ __forceinline__ uint32_t stage_off(int kt) {
    return (uint32_t)(OFF_ST + (kt % 3) * STAGE_SZ);
}
}  // namespace

__global__ __launch_bounds__(NT, 3)
void sdpa_kernel(const float* __restrict__ q, float* __restrict__ out) {
    extern __shared__ char smem[];
    const uint32_t sb = smem_u32(smem);
    const int tid = threadIdx.x, lane = tid & 31, wid = tid >> 5;
    const int g = lane >> 2, m = lane & 3;
    const bool modd = (m & 1) != 0;
    const int qcol = modd ? 2 * m + 6 : 2 * m;
    const int rs = wid * 32;
    const uint32_t xr = (uint32_t)((lane & 7) << 4);

    const int bh = blockIdx.y, qb = blockIdx.x;
    const int cta = bh * (Sc / QT) + qb;
    const float* qg   = q + ((long long)bh * Sc + qb * QT) * Dc;
    const __half* kgb = g_kh + (long long)bh * Sc * Dc;
    const __half* vgb = g_vh + (long long)bh * Sc * Dc;
    float* score = out + (long long)bh * Sc * Sc + (long long)(qb * QT) * Sc;
    float* ctx   = out + SCORE_ELEMS + ((long long)bh * Sc + qb * QT) * Dc;
    uint4* us = g_us + ((size_t)cta * NKT * NT + tid) * 8;   // stride NT*8 per kt

    // ---- prologue: async K+V tiles 0,1; convert Q fp32->fp16 meanwhile ----
    load_tile64(sb + stage_off(0), kgb, tid);
    load_tile64(sb + stage_off(0) + V_IN_STAGE, vgb, tid);
    CP_COMMIT();
    load_tile64(sb + stage_off(1), kgb + (long long)KT * Dc, tid);
    load_tile64(sb + stage_off(1) + V_IN_STAGE, vgb + (long long)KT * Dc, tid);
    CP_COMMIT();
    #pragma unroll
    for (int i0 = 0; i0 < 16; i0++) {
        int i = tid + i0 * NT;
        int r = i >> 4, c4 = (i & 15) << 2;
        float4 x = *reinterpret_cast<const float4*>(qg + r * Dc + c4);
        *reinterpret_cast<uint2*>(smem + OFF_Q + swz((uint32_t)(r * 128 + c4 * 2))) =
            make_uint2(h2u(__floats2half2_rn(x.x, x.y)), h2u(__floats2half2_rn(x.z, x.w)));
    }
    CP_WAIT1();
    __syncthreads();

    uint32_t qf[4][2][4];
    #pragma unroll
    for (int mf = 0; mf < 2; mf++) {
        uint32_t aq = sb + OFF_Q + (uint32_t)((rs + mf * 16 + (lane & 15)) * 128);
        #pragma unroll
        for (int kk = 0; kk < 4; kk++)
            ldsm4(qf[kk][mf], aq + (((uint32_t)(kk * 32 + ((lane >> 4) * 16))) ^ xr));
    }

    const uint32_t krow = (uint32_t)((((lane >> 4) << 3) + (lane & 7)) * 128);
    const uint32_t vrow = (uint32_t)((lane & 15) * 128);
    const uint32_t vc0 = (uint32_t)((lane >> 4) * 16);
    const uint32_t kfr = (uint32_t)(((lane >> 3) & 1) * 16);

    // ============ single compute pass: u, rowsum, scratch, unnormalized PV ============
    float rsum[2][2] = {{0.f, 0.f}, {0.f, 0.f}};
    float cc[2][8][4];
    #pragma unroll
    for (int mf = 0; mf < 2; mf++)
        #pragma unroll
        for (int nf = 0; nf < 8; nf++)
            cc[mf][nf][0] = cc[mf][nf][1] = cc[mf][nf][2] = cc[mf][nf][3] = 0.f;

    for (int kt = 0; kt < NKT; kt++) {
        CP_WAIT1();
        __syncthreads();
        if (kt + 2 < NKT) {
            load_tile64(sb + stage_off(kt + 2), kgb + (long long)(kt + 2) * KT * Dc, tid);
            load_tile64(sb + stage_off(kt + 2) + V_IN_STAGE,
                        vgb + (long long)(kt + 2) * KT * Dc, tid);
        }
        CP_COMMIT();

        const uint32_t kbase = sb + stage_off(kt) + krow;
        const uint32_t vbase = sb + stage_off(kt) + V_IN_STAGE + vrow;
        uint4* ukt = us + (size_t)kt * (NT * 8);

        #pragma unroll
        for (int nb2 = 0; nb2 < 2; nb2++) {
            float acc[2][2][2][4];
            #pragma unroll
            for (int mf = 0; mf < 2; mf++)
                #pragma unroll
                for (int c = 0; c < 2; c++)
                    #pragma unroll
                    for (int j = 0; j < 2; j++)
                        acc[mf][c][j][0] = acc[mf][c][j][1] =
                        acc[mf][c][j][2] = acc[mf][c][j][3] = 0.f;
            #pragma unroll
            for (int kk = 0; kk < 4; kk++) {
                uint32_t kb = (((uint32_t)(kk * 32)) + kfr) ^ xr;
                #pragma unroll
                for (int c = 0; c < 2; c++) {
                    uint32_t B[4];
                    ldsm4(B, kbase + (uint32_t)((2 * nb2 + c) * 2048) + kb);
                    #pragma unroll
                    for (int mf = 0; mf < 2; mf++) {
                        mma16816(acc[mf][c][0], qf[kk][mf], B[0], B[1]);
                        mma16816(acc[mf][c][1], qf[kk][mf], B[2], B[3]);
                    }
                }
            }

            // u = exp2(s*EC) (UNNORMALIZED); rowsum; pack fp16; stash to scratch
            uint32_t pa[2][2][4];
            #pragma unroll
            for (int mf = 0; mf < 2; mf++) {
                #pragma unroll
                for (int c = 0; c < 2; c++) {
                    float p00 = ex2(acc[mf][c][0][0] * EC);
                    float p01 = ex2(acc[mf][c][0][1] * EC);
                    float p02 = ex2(acc[mf][c][0][2] * EC);
                    float p03 = ex2(acc[mf][c][0][3] * EC);
                    float p10 = ex2(acc[mf][c][1][0] * EC);
                    float p11 = ex2(acc[mf][c][1][1] * EC);
                    float p12 = ex2(acc[mf][c][1][2] * EC);
                    float p13 = ex2(acc[mf][c][1][3] * EC);
                    rsum[mf][0] += (p00 + p01) + (p10 + p11);
                    rsum[mf][1] += (p02 + p03) + (p12 + p13);
                    pa[mf][c][0] = h2u(__floats2half2_rn(p00, p01));
                    pa[mf][c][1] = h2u(__floats2half2_rn(p02, p03));
                    pa[mf][c][2] = h2u(__floats2half2_rn(p10, p11));
                    pa[mf][c][3] = h2u(__floats2half2_rn(p12, p13));
                    ukt[nb2 * 4 + mf * 2 + c] =
                        make_uint4(pa[mf][c][0], pa[mf][c][1], pa[mf][c][2], pa[mf][c][3]);
                }
            }

            // PV with unnormalized u (fix by inv at the end)
            #pragma unroll
            for (int db = 0; db < 4; db++) {
                uint32_t B0[4], B1[4];
                uint32_t vo = (vc0 + (uint32_t)(db * 32)) ^ xr;
                ldsm4t(B0, vbase + (uint32_t)((2 * nb2) * 2048) + vo);
                ldsm4t(B1, vbase + (uint32_t)((2 * nb2 + 1) * 2048) + vo);
                #pragma unroll
                for (int mf = 0; mf < 2; mf++) {
                    mma16816(cc[mf][2 * db],     pa[mf][0], B0[0], B0[1]);
                    mma16816(cc[mf][2 * db + 1], pa[mf][0], B0[2], B0[3]);
                    mma16816(cc[mf][2 * db],     pa[mf][1], B1[0], B1[1]);
                    mma16816(cc[mf][2 * db + 1], pa[mf][1], B1[2], B1[3]);
                }
            }
        }
    }

    // ---- rowsum reduce -> inv; write normalized context (STG.128) ----
    float inv[2][2];
    #pragma unroll
    for (int mf = 0; mf < 2; mf++)
        #pragma unroll
        for (int h = 0; h < 2; h++) {
            float s = rsum[mf][h];
            s += __shfl_xor_sync(0xffffffffu, s, 1);
            s += __shfl_xor_sync(0xffffffffu, s, 2);
            inv[mf][h] = 1.f / s;
        }

    #pragma unroll
    for (int mf = 0; mf < 2; mf++) {
        const int r0 = rs + mf * 16 + g, r1 = r0 + 8;
        #pragma unroll
        for (int d = 0; d < 4; d++) {
            int colG = d * 16 + qcol;
            float4 q0 = quad_merge(modd,
                cc[mf][2 * d][0] * inv[mf][0], cc[mf][2 * d][1] * inv[mf][0],
                cc[mf][2 * d + 1][0] * inv[mf][0], cc[mf][2 * d + 1][1] * inv[mf][0]);
            __stcs(reinterpret_cast<float4*>(ctx + (long long)r0 * Dc + colG), q0);
            float4 q1 = quad_merge(modd,
                cc[mf][2 * d][2] * inv[mf][1], cc[mf][2 * d][3] * inv[mf][1],
                cc[mf][2 * d + 1][2] * inv[mf][1], cc[mf][2 * d + 1][3] * inv[mf][1]);
            __stcs(reinterpret_cast<float4*>(ctx + (long long)r1 * Dc + colG), q1);
        }
    }

    // ============ streaming normalize tail: scores = u * inv ============
    // Same thread re-reads its own fragments (ST->LD same thread: ordered).
    #pragma unroll 2
    for (int kt = 0; kt < NKT; kt++) {
        const uint4* ukt = us + (size_t)kt * (NT * 8);
        uint4 ub[8];
        #pragma unroll
        for (int i = 0; i < 8; i++) ub[i] = ukt[i];
        #pragma unroll
        for (int nb2 = 0; nb2 < 2; nb2++) {
            #pragma unroll
            for (int mf = 0; mf < 2; mf++) {
                const int r0 = rs + mf * 16 + g, r1 = r0 + 8;
                #pragma unroll
                for (int c = 0; c < 2; c++) {
                    uint4 u = ub[nb2 * 4 + mf * 2 + c];
                    float2 f0 = __half22float2(u2h(u.x));   // p00,p01 (r0, j0)
                    float2 f1 = __half22float2(u2h(u.y));   // p02,p03 (r1, j0)
                    float2 f2 = __half22float2(u2h(u.z));   // p10,p11 (r0, j1)
                    float2 f3 = __half22float2(u2h(u.w));   // p12,p13 (r1, j1)
                    int colG = kt * KT + (2 * nb2 + c) * 16 + qcol;
                    float4 q0 = quad_merge(modd, f0.x * inv[mf][0], f0.y * inv[mf][0],
                                                 f2.x * inv[mf][0], f2.y * inv[mf][0]);
                    __stcs(reinterpret_cast<float4*>(score + (long long)r0 * Sc + colG), q0);
                    float4 q1 = quad_merge(modd, f1.x * inv[mf][1], f1.y * inv[mf][1],
                                                 f3.x * inv[mf][1], f3.y * inv[mf][1]);
                    __stcs(reinterpret_cast<float4*>(score + (long long)r1 * Sc + colG), q1);
                }
            }
        }
    }
}

extern "C" void kernel_launch(void* const* d_in, const int* in_sizes, int n_in,
                              void* d_out, int out_size) {
    (void)in_sizes; (void)n_in; (void)out_size;
    const float* q = (const float*)d_in[0];
    const float4* k = (const float4*)d_in[1];
    const float4* v = (const float4*)d_in[2];
    float* out = (float*)d_out;

    cvt_kernel<<<(2 * N4 + 255) / 256, 256>>>(k, v);

    cudaFuncSetAttribute(sdpa_kernel,
                         cudaFuncAttributeMaxDynamicSharedMemorySize, SMEM_TOTAL);
    dim3 grid(Sc / QT, Bc * Hc);  // 8 x 96
    sdpa_kernel<<<grid, NT, SMEM_TOTAL>>>(q, out);
}

// round 15
// speedup vs baseline: 1.3363x; 1.3363x over previous
#include <cuda_runtime.h>
#include <cuda_fp16.h>
#include <cstdint>

// R11 base (verified passing) + ONE change: normalization folded into ex2
// argument (p = ex2(acc*EC + l2i), l2i = -lg2(rowsum)). Everything else
// identical: 4 warps x 32 q-rows, 3 CTAs/SM, 3-stage (K+V) cp.async pipeline
// in BOTH passes (wait_group 1), register-resident P, quad_merge STG.128.

namespace {
constexpr int Bc = 8, Hc = 12, Sc = 1024, Dc = 64;
constexpr int QT = 128, KT = 64, NKT = Sc / KT;
constexpr long long SCORE_ELEMS = (long long)Bc * Hc * Sc * Sc;
constexpr float EC = 0.18033688011112042f;  // log2(e) / 8
constexpr int NELEM = Bc * Hc * Sc * Dc;
constexpr int N4 = NELEM / 4;
constexpr int NT = 128;

constexpr int OFF_Q = 0;
constexpr int OFF_ST = 16384;
constexpr int STAGE_SZ = 16384, V_IN_STAGE = 8192;
constexpr int SMEM_TOTAL = OFF_ST + 3 * STAGE_SZ;  // 65536

__device__ __forceinline__ uint32_t swz(uint32_t off) { return off ^ ((off >> 3) & 0x70); }
__device__ __forceinline__ uint32_t smem_u32(const void* p) {
    uint32_t a;
    asm("{ .reg .u64 t; cvta.to.shared.u64 t, %1; cvt.u32.u64 %0, t; }" : "=r"(a) : "l"(p));
    return a;
}
__device__ __forceinline__ uint32_t h2u(__half2 h) { return *reinterpret_cast<uint32_t*>(&h); }
__device__ __forceinline__ float ex2(float x) {
    float r;
    asm("ex2.approx.f32 %0, %1;" : "=f"(r) : "f"(x));
    return r;
}
__device__ __forceinline__ float lg2(float x) {
    float r;
    asm("lg2.approx.f32 %0, %1;" : "=f"(r) : "f"(x));
    return r;
}
__device__ __forceinline__ void ldsm4(uint32_t r[4], uint32_t a) {
    asm volatile("ldmatrix.sync.aligned.m8n8.x4.shared.b16 {%0,%1,%2,%3}, [%4];"
                 : "=r"(r[0]), "=r"(r[1]), "=r"(r[2]), "=r"(r[3]) : "r"(a));
}
__device__ __forceinline__ void ldsm4t(uint32_t r[4], uint32_t a) {
    asm volatile("ldmatrix.sync.aligned.m8n8.x4.trans.shared.b16 {%0,%1,%2,%3}, [%4];"
                 : "=r"(r[0]), "=r"(r[1]), "=r"(r[2]), "=r"(r[3]) : "r"(a));
}
__device__ __forceinline__ void mma16816(float c[4], const uint32_t a[4],
                                         uint32_t b0, uint32_t b1) {
    asm volatile(
        "mma.sync.aligned.m16n8k16.row.col.f32.f16.f16.f32 "
        "{%0,%1,%2,%3}, {%4,%5,%6,%7}, {%8,%9}, {%0,%1,%2,%3};"
        : "+f"(c[0]), "+f"(c[1]), "+f"(c[2]), "+f"(c[3])
        : "r"(a[0]), "r"(a[1]), "r"(a[2]), "r"(a[3]), "r"(b0), "r"(b1));
}
__device__ __forceinline__ void cpa16(uint32_t d, const void* s) {
    asm volatile("cp.async.cg.shared.global [%0], [%1], 16;" :: "r"(d), "l"(s) : "memory");
}
#define CP_COMMIT() asm volatile("cp.async.commit_group;" ::: "memory")
#define CP_WAIT1()  asm volatile("cp.async.wait_group 1;" ::: "memory")

__device__ __forceinline__ float4 quad_merge(bool odd, float e0, float e1,
                                             float o0, float o1) {
    float sx = odd ? e0 : o0, sy = odd ? e1 : o1;
    float rx = __shfl_xor_sync(0xffffffffu, sx, 1);
    float ry = __shfl_xor_sync(0xffffffffu, sy, 1);
    return odd ? make_float4(rx, ry, o0, o1) : make_float4(e0, e1, rx, ry);
}
}  // namespace

__device__ __align__(16) __half g_kh[NELEM];
__device__ __align__(16) __half g_vh[NELEM];

__global__ __launch_bounds__(256)
void cvt_kernel(const float4* __restrict__ k, const float4* __restrict__ v) {
    int i = blockIdx.x * blockDim.x + threadIdx.x;
    const float4* src;
    uint2* dst;
    int j;
    if (i < N4) { src = k; dst = reinterpret_cast<uint2*>(g_kh); j = i; }
    else        { src = v; dst = reinterpret_cast<uint2*>(g_vh); j = i - N4; }
    float4 x = src[j];
    dst[j] = make_uint2(h2u(__floats2half2_rn(x.x, x.y)), h2u(__floats2half2_rn(x.z, x.w)));
}

namespace {
__device__ __forceinline__ void load_tile64(uint32_t dstBase, const __half* gsrc, int tid) {
    #pragma unroll
    for (int i = 0; i < 4; i++) {
        int c = tid + i * NT;
        int r = c >> 3, ch = c & 7;
        cpa16(dstBase + swz((uint32_t)(r * 128 + ch * 16)), gsrc + r * 64 + ch * 8);
    }
}
__device__ __forceinline__ uint32_t stage_off(int kt) {
    return (uint32_t)(OFF_ST + (kt % 3) * STAGE_SZ);
}
}  // namespace

__global__ __launch_bounds__(NT, 3)
void sdpa_kernel(const float* __restrict__ q, float* __restrict__ out) {
    extern __shared__ char smem[];
    const uint32_t sb = smem_u32(smem);
    const int tid = threadIdx.x, lane = tid & 31, wid = tid >> 5;
    const int g = lane >> 2, m = lane & 3;
    const bool modd = (m & 1) != 0;
    const int qcol = modd ? 2 * m + 6 : 2 * m;
    const int rs = wid * 32;
    const uint32_t xr = (uint32_t)((lane & 7) << 4);

    const int bh = blockIdx.y, qb = blockIdx.x;
    const float* qg   = q + ((long long)bh * Sc + qb * QT) * Dc;
    const __half* kgb = g_kh + (long long)bh * Sc * Dc;
    const __half* vgb = g_vh + (long long)bh * Sc * Dc;
    float* score = out + (long long)bh * Sc * Sc + (long long)(qb * QT) * Sc;
    float* ctx   = out + SCORE_ELEMS + ((long long)bh * Sc + qb * QT) * Dc;

    // ---- prologue: async K tiles 0,1; convert Q fp32->fp16 meanwhile ----
    load_tile64(sb + stage_off(0), kgb, tid);
    CP_COMMIT();
    load_tile64(sb + stage_off(1), kgb + (long long)KT * Dc, tid);
    CP_COMMIT();
    #pragma unroll
    for (int i0 = 0; i0 < 16; i0++) {
        int i = tid + i0 * NT;
        int r = i >> 4, c4 = (i & 15) << 2;
        float4 x = *reinterpret_cast<const float4*>(qg + r * Dc + c4);
        *reinterpret_cast<uint2*>(smem + OFF_Q + swz((uint32_t)(r * 128 + c4 * 2))) =
            make_uint2(h2u(__floats2half2_rn(x.x, x.y)), h2u(__floats2half2_rn(x.z, x.w)));
    }
    CP_WAIT1();
    __syncthreads();

    uint32_t qf[4][2][4];
    #pragma unroll
    for (int mf = 0; mf < 2; mf++) {
        uint32_t aq = sb + OFF_Q + (uint32_t)((rs + mf * 16 + (lane & 15)) * 128);
        #pragma unroll
        for (int kk = 0; kk < 4; kk++)
            ldsm4(qf[kk][mf], aq + (((uint32_t)(kk * 32 + ((lane >> 4) * 16))) ^ xr));
    }

    const uint32_t krow = (uint32_t)((((lane >> 4) << 3) + (lane & 7)) * 128);
    const uint32_t vrow = (uint32_t)((lane & 15) * 128);
    const uint32_t vc0 = (uint32_t)((lane >> 4) * 16);
    const uint32_t kfr = (uint32_t)(((lane >> 3) & 1) * 16);

    // =================== pass A: row sums (full-tile ILP) ===================
    float rsum[2][2] = {{0.f, 0.f}, {0.f, 0.f}};
    for (int kt = 0; kt < NKT; kt++) {
        CP_WAIT1();
        __syncthreads();
        if (kt + 2 < NKT)
            load_tile64(sb + stage_off(kt + 2), kgb + (long long)(kt + 2) * KT * Dc, tid);
        CP_COMMIT();

        const uint32_t kbase = sb + stage_off(kt) + krow;
        float acc[2][8][4];
        #pragma unroll
        for (int mf = 0; mf < 2; mf++)
            #pragma unroll
            for (int nf = 0; nf < 8; nf++)
                acc[mf][nf][0] = acc[mf][nf][1] = acc[mf][nf][2] = acc[mf][nf][3] = 0.f;
        #pragma unroll
        for (int kk = 0; kk < 4; kk++) {
            uint32_t kb = (((uint32_t)(kk * 32)) + kfr) ^ xr;
            #pragma unroll
            for (int nb = 0; nb < 4; nb++) {
                uint32_t B[4];
                ldsm4(B, kbase + (uint32_t)(nb * 2048) + kb);
                #pragma unroll
                for (int mf = 0; mf < 2; mf++) {
                    mma16816(acc[mf][2 * nb],     qf[kk][mf], B[0], B[1]);
                    mma16816(acc[mf][2 * nb + 1], qf[kk][mf], B[2], B[3]);
                }
            }
        }
        #pragma unroll
        for (int mf = 0; mf < 2; mf++)
            #pragma unroll
            for (int nf = 0; nf < 8; nf++) {
                rsum[mf][0] += ex2(acc[mf][nf][0] * EC) + ex2(acc[mf][nf][1] * EC);
                rsum[mf][1] += ex2(acc[mf][nf][2] * EC) + ex2(acc[mf][nf][3] * EC);
            }
    }

    // ---- transition: issue pass-B stages 0,1 while reducing ----
    __syncthreads();
    load_tile64(sb + stage_off(0), kgb, tid);
    load_tile64(sb + stage_off(0) + V_IN_STAGE, vgb, tid);
    CP_COMMIT();
    load_tile64(sb + stage_off(1), kgb + (long long)KT * Dc, tid);
    load_tile64(sb + stage_off(1) + V_IN_STAGE, vgb + (long long)KT * Dc, tid);
    CP_COMMIT();

    float l2i[2][2];
    #pragma unroll
    for (int mf = 0; mf < 2; mf++)
        #pragma unroll
        for (int h = 0; h < 2; h++) {
            float s = rsum[mf][h];
            s += __shfl_xor_sync(0xffffffffu, s, 1);
            s += __shfl_xor_sync(0xffffffffu, s, 2);
            l2i[mf][h] = -lg2(s);
        }

    // =================== pass B: scores + context ===================
    float cc[2][8][4];
    #pragma unroll
    for (int mf = 0; mf < 2; mf++)
        #pragma unroll
        for (int nf = 0; nf < 8; nf++)
            cc[mf][nf][0] = cc[mf][nf][1] = cc[mf][nf][2] = cc[mf][nf][3] = 0.f;

    for (int kt = 0; kt < NKT; kt++) {
        CP_WAIT1();
        __syncthreads();
        if (kt + 2 < NKT) {
            load_tile64(sb + stage_off(kt + 2), kgb + (long long)(kt + 2) * KT * Dc, tid);
            load_tile64(sb + stage_off(kt + 2) + V_IN_STAGE,
                        vgb + (long long)(kt + 2) * KT * Dc, tid);
        }
        CP_COMMIT();

        const uint32_t kbase = sb + stage_off(kt) + krow;
        const uint32_t vbase = sb + stage_off(kt) + V_IN_STAGE + vrow;

        #pragma unroll
        for (int nb2 = 0; nb2 < 2; nb2++) {
            float acc[2][2][2][4];
            #pragma unroll
            for (int mf = 0; mf < 2; mf++)
                #pragma unroll
                for (int c = 0; c < 2; c++)
                    #pragma unroll
                    for (int j = 0; j < 2; j++)
                        acc[mf][c][j][0] = acc[mf][c][j][1] =
                        acc[mf][c][j][2] = acc[mf][c][j][3] = 0.f;
            #pragma unroll
            for (int kk = 0; kk < 4; kk++) {
                uint32_t kb = (((uint32_t)(kk * 32)) + kfr) ^ xr;
                #pragma unroll
                for (int c = 0; c < 2; c++) {
                    uint32_t B[4];
                    ldsm4(B, kbase + (uint32_t)((2 * nb2 + c) * 2048) + kb);
                    #pragma unroll
                    for (int mf = 0; mf < 2; mf++) {
                        mma16816(acc[mf][c][0], qf[kk][mf], B[0], B[1]);
                        mma16816(acc[mf][c][1], qf[kk][mf], B[2], B[3]);
                    }
                }
            }

            // p = ex2(acc*EC + l2i); pack P; coalesced STG.128 scores
            uint32_t pa[2][2][4];
            #pragma unroll
            for (int mf = 0; mf < 2; mf++) {
                const int r0 = rs + mf * 16 + g, r1 = r0 + 8;
                #pragma unroll
                for (int c = 0; c < 2; c++) {
                    float p00 = ex2(__fmaf_rn(acc[mf][c][0][0], EC, l2i[mf][0]));
                    float p01 = ex2(__fmaf_rn(acc[mf][c][0][1], EC, l2i[mf][0]));
                    float p02 = ex2(__fmaf_rn(acc[mf][c][0][2], EC, l2i[mf][1]));
                    float p03 = ex2(__fmaf_rn(acc[mf][c][0][3], EC, l2i[mf][1]));
                    float p10 = ex2(__fmaf_rn(acc[mf][c][1][0], EC, l2i[mf][0]));
                    float p11 = ex2(__fmaf_rn(acc[mf][c][1][1], EC, l2i[mf][0]));
                    float p12 = ex2(__fmaf_rn(acc[mf][c][1][2], EC, l2i[mf][1]));
                    float p13 = ex2(__fmaf_rn(acc[mf][c][1][3], EC, l2i[mf][1]));
                    pa[mf][c][0] = h2u(__floats2half2_rn(p00, p01));
                    pa[mf][c][1] = h2u(__floats2half2_rn(p02, p03));
                    pa[mf][c][2] = h2u(__floats2half2_rn(p10, p11));
                    pa[mf][c][3] = h2u(__floats2half2_rn(p12, p13));

                    int colG = kt * KT + (2 * nb2 + c) * 16 + qcol;
                    float4 q0 = quad_merge(modd, p00, p01, p10, p11);
                    __stcs(reinterpret_cast<float4*>(score + (long long)r0 * Sc + colG), q0);
                    float4 q1 = quad_merge(modd, p02, p03, p12, p13);
                    __stcs(reinterpret_cast<float4*>(score + (long long)r1 * Sc + colG), q1);
                }
            }

            // PV for this 32-seq chunk pair
            #pragma unroll
            for (int db = 0; db < 4; db++) {
                uint32_t B0[4], B1[4];
                uint32_t vo = (vc0 + (uint32_t)(db * 32)) ^ xr;
                ldsm4t(B0, vbase + (uint32_t)((2 * nb2) * 2048) + vo);
                ldsm4t(B1, vbase + (uint32_t)((2 * nb2 + 1) * 2048) + vo);
                #pragma unroll
                for (int mf = 0; mf < 2; mf++) {
                    mma16816(cc[mf][2 * db],     pa[mf][0], B0[0], B0[1]);
                    mma16816(cc[mf][2 * db + 1], pa[mf][0], B0[2], B0[3]);
                    mma16816(cc[mf][2 * db],     pa[mf][1], B1[0], B1[1]);
                    mma16816(cc[mf][2 * db + 1], pa[mf][1], B1[2], B1[3]);
                }
            }
        }
    }

    // ---- write context (P normalized -> no scale; coalesced STG.128) ----
    #pragma unroll
    for (int mf = 0; mf < 2; mf++) {
        const int r0 = rs + mf * 16 + g, r1 = r0 + 8;
        #pragma unroll
        for (int d = 0; d < 4; d++) {
            int colG = d * 16 + qcol;
            float4 q0 = quad_merge(modd, cc[mf][2 * d][0], cc[mf][2 * d][1],
                                          cc[mf][2 * d + 1][0], cc[mf][2 * d + 1][1]);
            __stcs(reinterpret_cast<float4*>(ctx + (long long)r0 * Dc + colG), q0);
            float4 q1 = quad_merge(modd, cc[mf][2 * d][2], cc[mf][2 * d][3],
                                          cc[mf][2 * d + 1][2], cc[mf][2 * d + 1][3]);
            __stcs(reinterpret_cast<float4*>(ctx + (long long)r1 * Dc + colG), q1);
        }
    }
}

extern "C" void kernel_launch(void* const* d_in, const int* in_sizes, int n_in,
                              void* d_out, int out_size) {
    (void)in_sizes; (void)n_in; (void)out_size;
    const float* q = (const float*)d_in[0];
    const float4* k = (const float4*)d_in[1];
    const float4* v = (const float4*)d_in[2];
    float* out = (float*)d_out;

    cvt_kernel<<<(2 * N4 + 255) / 256, 256>>>(k, v);

    cudaFuncSetAttribute(sdpa_kernel,
                         cudaFuncAttributeMaxDynamicSharedMemorySize, SMEM_TOTAL);
    dim3 grid(Sc / QT, Bc * Hc);  // 8 x 96
    sdpa_kernel<<<grid, NT, SMEM_TOTAL>>>(q, out);
}

// round 16
// speedup vs baseline: 1.4514x; 1.0862x over previous
#include <cuda_runtime.h>
#include <cuda_fp16.h>
#include <cstdint>

// fp16 mma.sync attention — R8 execution shape (2 CTAs/SM, full-tile 16-chain
// ILP in both passes) + verified improvements: K/V-only cvt, Q converted in
// prologue, 3-stage cp.async (wait_group 1) both passes, quad_merge STG.128
// stores, lg2-fold normalize (p = ex2(acc*EC + l2i)). Register-resident P.

namespace {
constexpr int Bc = 8, Hc = 12, Sc = 1024, Dc = 64;
constexpr int QT = 128, KT = 64, NKT = Sc / KT;
constexpr long long SCORE_ELEMS = (long long)Bc * Hc * Sc * Sc;
constexpr float EC = 0.18033688011112042f;  // log2(e) / 8
constexpr int NELEM = Bc * Hc * Sc * Dc;
constexpr int N4 = NELEM / 4;
constexpr int NT = 128;

constexpr int OFF_Q = 0;
constexpr int OFF_ST = 16384;
constexpr int STAGE_SZ = 16384, V_IN_STAGE = 8192;
constexpr int SMEM_TOTAL = OFF_ST + 3 * STAGE_SZ;  // 65536 (2 CTAs -> 128KB/SM)

__device__ __forceinline__ uint32_t swz(uint32_t off) { return off ^ ((off >> 3) & 0x70); }
__device__ __forceinline__ uint32_t smem_u32(const void* p) {
    uint32_t a;
    asm("{ .reg .u64 t; cvta.to.shared.u64 t, %1; cvt.u32.u64 %0, t; }" : "=r"(a) : "l"(p));
    return a;
}
__device__ __forceinline__ uint32_t h2u(__half2 h) { return *reinterpret_cast<uint32_t*>(&h); }
__device__ __forceinline__ float ex2(float x) {
    float r;
    asm("ex2.approx.f32 %0, %1;" : "=f"(r) : "f"(x));
    return r;
}
__device__ __forceinline__ float lg2(float x) {
    float r;
    asm("lg2.approx.f32 %0, %1;" : "=f"(r) : "f"(x));
    return r;
}
__device__ __forceinline__ void ldsm4(uint32_t r[4], uint32_t a) {
    asm volatile("ldmatrix.sync.aligned.m8n8.x4.shared.b16 {%0,%1,%2,%3}, [%4];"
                 : "=r"(r[0]), "=r"(r[1]), "=r"(r[2]), "=r"(r[3]) : "r"(a));
}
__device__ __forceinline__ void ldsm4t(uint32_t r[4], uint32_t a) {
    asm volatile("ldmatrix.sync.aligned.m8n8.x4.trans.shared.b16 {%0,%1,%2,%3}, [%4];"
                 : "=r"(r[0]), "=r"(r[1]), "=r"(r[2]), "=r"(r[3]) : "r"(a));
}
__device__ __forceinline__ void mma16816(float c[4], const uint32_t a[4],
                                         uint32_t b0, uint32_t b1) {
    asm volatile(
        "mma.sync.aligned.m16n8k16.row.col.f32.f16.f16.f32 "
        "{%0,%1,%2,%3}, {%4,%5,%6,%7}, {%8,%9}, {%0,%1,%2,%3};"
        : "+f"(c[0]), "+f"(c[1]), "+f"(c[2]), "+f"(c[3])
        : "r"(a[0]), "r"(a[1]), "r"(a[2]), "r"(a[3]), "r"(b0), "r"(b1));
}
__device__ __forceinline__ void cpa16(uint32_t d, const void* s) {
    asm volatile("cp.async.cg.shared.global [%0], [%1], 16;" :: "r"(d), "l"(s) : "memory");
}
#define CP_COMMIT() asm volatile("cp.async.commit_group;" ::: "memory")
#define CP_WAIT1()  asm volatile("cp.async.wait_group 1;" ::: "memory")

__device__ __forceinline__ float4 quad_merge(bool odd, float e0, float e1,
                                             float o0, float o1) {
    float sx = odd ? e0 : o0, sy = odd ? e1 : o1;
    float rx = __shfl_xor_sync(0xffffffffu, sx, 1);
    float ry = __shfl_xor_sync(0xffffffffu, sy, 1);
    return odd ? make_float4(rx, ry, o0, o1) : make_float4(e0, e1, rx, ry);
}
}  // namespace

__device__ __align__(16) __half g_kh[NELEM];
__device__ __align__(16) __half g_vh[NELEM];

__global__ __launch_bounds__(256)
void cvt_kernel(const float4* __restrict__ k, const float4* __restrict__ v) {
    int i = blockIdx.x * blockDim.x + threadIdx.x;
    const float4* src;
    uint2* dst;
    int j;
    if (i < N4) { src = k; dst = reinterpret_cast<uint2*>(g_kh); j = i; }
    else        { src = v; dst = reinterpret_cast<uint2*>(g_vh); j = i - N4; }
    float4 x = src[j];
    dst[j] = make_uint2(h2u(__floats2half2_rn(x.x, x.y)), h2u(__floats2half2_rn(x.z, x.w)));
}

namespace {
__device__ __forceinline__ void load_tile64(uint32_t dstBase, const __half* gsrc, int tid) {
    #pragma unroll
    for (int i = 0; i < 4; i++) {
        int c = tid + i * NT;
        int r = c >> 3, ch = c & 7;
        cpa16(dstBase + swz((uint32_t)(r * 128 + ch * 16)), gsrc + r * 64 + ch * 8);
    }
}
__device__ __forceinline__ uint32_t stage_off(int kt) {
    return (uint32_t)(OFF_ST + (kt % 3) * STAGE_SZ);
}
}  // namespace

__global__ __launch_bounds__(NT, 2)
void sdpa_kernel(const float* __restrict__ q, float* __restrict__ out) {
    extern __shared__ char smem[];
    const uint32_t sb = smem_u32(smem);
    const int tid = threadIdx.x, lane = tid & 31, wid = tid >> 5;
    const int g = lane >> 2, m = lane & 3;
    const bool modd = (m & 1) != 0;
    const int qcol = modd ? 2 * m + 6 : 2 * m;
    const int rs = wid * 32;
    const uint32_t xr = (uint32_t)((lane & 7) << 4);

    const int bh = blockIdx.y, qb = blockIdx.x;
    const float* qg   = q + ((long long)bh * Sc + qb * QT) * Dc;
    const __half* kgb = g_kh + (long long)bh * Sc * Dc;
    const __half* vgb = g_vh + (long long)bh * Sc * Dc;
    float* score = out + (long long)bh * Sc * Sc + (long long)(qb * QT) * Sc;
    float* ctx   = out + SCORE_ELEMS + ((long long)bh * Sc + qb * QT) * Dc;

    // ---- prologue: async K tiles 0,1; convert Q fp32->fp16 meanwhile ----
    load_tile64(sb + stage_off(0), kgb, tid);
    CP_COMMIT();
    load_tile64(sb + stage_off(1), kgb + (long long)KT * Dc, tid);
    CP_COMMIT();
    #pragma unroll
    for (int i0 = 0; i0 < 16; i0++) {
        int i = tid + i0 * NT;
        int r = i >> 4, c4 = (i & 15) << 2;
        float4 x = *reinterpret_cast<const float4*>(qg + r * Dc + c4);
        *reinterpret_cast<uint2*>(smem + OFF_Q + swz((uint32_t)(r * 128 + c4 * 2))) =
            make_uint2(h2u(__floats2half2_rn(x.x, x.y)), h2u(__floats2half2_rn(x.z, x.w)));
    }
    CP_WAIT1();
    __syncthreads();

    uint32_t qf[4][2][4];
    #pragma unroll
    for (int mf = 0; mf < 2; mf++) {
        uint32_t aq = sb + OFF_Q + (uint32_t)((rs + mf * 16 + (lane & 15)) * 128);
        #pragma unroll
        for (int kk = 0; kk < 4; kk++)
            ldsm4(qf[kk][mf], aq + (((uint32_t)(kk * 32 + ((lane >> 4) * 16))) ^ xr));
    }

    const uint32_t krow = (uint32_t)((((lane >> 4) << 3) + (lane & 7)) * 128);
    const uint32_t vrow = (uint32_t)((lane & 15) * 128);
    const uint32_t vc0 = (uint32_t)((lane >> 4) * 16);
    const uint32_t kfr = (uint32_t)(((lane >> 3) & 1) * 16);

    // =================== pass A: row sums (full-tile ILP) ===================
    float rsum[2][2] = {{0.f, 0.f}, {0.f, 0.f}};
    for (int kt = 0; kt < NKT; kt++) {
        CP_WAIT1();
        __syncthreads();
        if (kt + 2 < NKT)
            load_tile64(sb + stage_off(kt + 2), kgb + (long long)(kt + 2) * KT * Dc, tid);
        CP_COMMIT();

        const uint32_t kbase = sb + stage_off(kt) + krow;
        float acc[2][8][4];
        #pragma unroll
        for (int mf = 0; mf < 2; mf++)
            #pragma unroll
            for (int nf = 0; nf < 8; nf++)
                acc[mf][nf][0] = acc[mf][nf][1] = acc[mf][nf][2] = acc[mf][nf][3] = 0.f;
        #pragma unroll
        for (int kk = 0; kk < 4; kk++) {
            uint32_t kb = (((uint32_t)(kk * 32)) + kfr) ^ xr;
            #pragma unroll
            for (int nb = 0; nb < 4; nb++) {
                uint32_t B[4];
                ldsm4(B, kbase + (uint32_t)(nb * 2048) + kb);
                #pragma unroll
                for (int mf = 0; mf < 2; mf++) {
                    mma16816(acc[mf][2 * nb],     qf[kk][mf], B[0], B[1]);
                    mma16816(acc[mf][2 * nb + 1], qf[kk][mf], B[2], B[3]);
                }
            }
        }
        #pragma unroll
        for (int mf = 0; mf < 2; mf++)
            #pragma unroll
            for (int nf = 0; nf < 8; nf++) {
                rsum[mf][0] += ex2(acc[mf][nf][0] * EC) + ex2(acc[mf][nf][1] * EC);
                rsum[mf][1] += ex2(acc[mf][nf][2] * EC) + ex2(acc[mf][nf][3] * EC);
            }
    }

    // ---- transition: issue pass-B stages 0,1 while reducing ----
    __syncthreads();
    load_tile64(sb + stage_off(0), kgb, tid);
    load_tile64(sb + stage_off(0) + V_IN_STAGE, vgb, tid);
    CP_COMMIT();
    load_tile64(sb + stage_off(1), kgb + (long long)KT * Dc, tid);
    load_tile64(sb + stage_off(1) + V_IN_STAGE, vgb + (long long)KT * Dc, tid);
    CP_COMMIT();

    float l2i[2][2];
    #pragma unroll
    for (int mf = 0; mf < 2; mf++)
        #pragma unroll
        for (int h = 0; h < 2; h++) {
            float s = rsum[mf][h];
            s += __shfl_xor_sync(0xffffffffu, s, 1);
            s += __shfl_xor_sync(0xffffffffu, s, 2);
            l2i[mf][h] = -lg2(s);
        }

    // ========= pass B: full-tile QK (16 chains) -> exp burst -> stores -> PV =========
    float cc[2][8][4];
    #pragma unroll
    for (int mf = 0; mf < 2; mf++)
        #pragma unroll
        for (int nf = 0; nf < 8; nf++)
            cc[mf][nf][0] = cc[mf][nf][1] = cc[mf][nf][2] = cc[mf][nf][3] = 0.f;

    for (int kt = 0; kt < NKT; kt++) {
        CP_WAIT1();
        __syncthreads();
        if (kt + 2 < NKT) {
            load_tile64(sb + stage_off(kt + 2), kgb + (long long)(kt + 2) * KT * Dc, tid);
            load_tile64(sb + stage_off(kt + 2) + V_IN_STAGE,
                        vgb + (long long)(kt + 2) * KT * Dc, tid);
        }
        CP_COMMIT();

        const uint32_t kbase = sb + stage_off(kt) + krow;
        const uint32_t vbase = sb + stage_off(kt) + V_IN_STAGE + vrow;

        // full-tile QK: 16 independent chains
        float acc[2][8][4];
        #pragma unroll
        for (int mf = 0; mf < 2; mf++)
            #pragma unroll
            for (int nf = 0; nf < 8; nf++)
                acc[mf][nf][0] = acc[mf][nf][1] = acc[mf][nf][2] = acc[mf][nf][3] = 0.f;
        #pragma unroll
        for (int kk = 0; kk < 4; kk++) {
            uint32_t kb = (((uint32_t)(kk * 32)) + kfr) ^ xr;
            #pragma unroll
            for (int nb = 0; nb < 4; nb++) {
                uint32_t B[4];
                ldsm4(B, kbase + (uint32_t)(nb * 2048) + kb);
                #pragma unroll
                for (int mf = 0; mf < 2; mf++) {
                    mma16816(acc[mf][2 * nb],     qf[kk][mf], B[0], B[1]);
                    mma16816(acc[mf][2 * nb + 1], qf[kk][mf], B[2], B[3]);
                }
            }
        }

        // exp burst: p = ex2(acc*EC + l2i), in place (high MUFU ILP)
        #pragma unroll
        for (int mf = 0; mf < 2; mf++)
            #pragma unroll
            for (int nf = 0; nf < 8; nf++) {
                acc[mf][nf][0] = ex2(__fmaf_rn(acc[mf][nf][0], EC, l2i[mf][0]));
                acc[mf][nf][1] = ex2(__fmaf_rn(acc[mf][nf][1], EC, l2i[mf][0]));
                acc[mf][nf][2] = ex2(__fmaf_rn(acc[mf][nf][2], EC, l2i[mf][1]));
                acc[mf][nf][3] = ex2(__fmaf_rn(acc[mf][nf][3], EC, l2i[mf][1]));
            }

        // coalesced STG.128 scores (quad_merge per 16-col chunk)
        #pragma unroll
        for (int mf = 0; mf < 2; mf++) {
            const int r0 = rs + mf * 16 + g, r1 = r0 + 8;
            #pragma unroll
            for (int c = 0; c < 4; c++) {
                int colG = kt * KT + c * 16 + qcol;
                float4 q0 = quad_merge(modd, acc[mf][2 * c][0], acc[mf][2 * c][1],
                                              acc[mf][2 * c + 1][0], acc[mf][2 * c + 1][1]);
                __stcs(reinterpret_cast<float4*>(score + (long long)r0 * Sc + colG), q0);
                float4 q1 = quad_merge(modd, acc[mf][2 * c][2], acc[mf][2 * c][3],
                                              acc[mf][2 * c + 1][2], acc[mf][2 * c + 1][3]);
                __stcs(reinterpret_cast<float4*>(score + (long long)r1 * Sc + colG), q1);
            }
        }

        // PV: pack P per 16-seq chunk from acc (C-frag == A-frag layout)
        #pragma unroll
        for (int c = 0; c < 4; c++) {
            uint32_t pa[2][4];
            #pragma unroll
            for (int mf = 0; mf < 2; mf++) {
                pa[mf][0] = h2u(__floats2half2_rn(acc[mf][2 * c][0],     acc[mf][2 * c][1]));
                pa[mf][1] = h2u(__floats2half2_rn(acc[mf][2 * c][2],     acc[mf][2 * c][3]));
                pa[mf][2] = h2u(__floats2half2_rn(acc[mf][2 * c + 1][0], acc[mf][2 * c + 1][1]));
                pa[mf][3] = h2u(__floats2half2_rn(acc[mf][2 * c + 1][2], acc[mf][2 * c + 1][3]));
            }
            uint32_t vb = vbase + (uint32_t)(c * 2048);
            #pragma unroll
            for (int db = 0; db < 4; db++) {
                uint32_t B[4];
                ldsm4t(B, vb + ((vc0 + (uint32_t)(db * 32)) ^ xr));
                #pragma unroll
                for (int mf = 0; mf < 2; mf++) {
                    mma16816(cc[mf][2 * db],     pa[mf], B[0], B[1]);
                    mma16816(cc[mf][2 * db + 1], pa[mf], B[2], B[3]);
                }
            }
        }
    }

    // ---- write context (P normalized -> no scale; coalesced STG.128) ----
    #pragma unroll
    for (int mf = 0; mf < 2; mf++) {
        const int r0 = rs + mf * 16 + g, r1 = r0 + 8;
        #pragma unroll
        for (int d = 0; d < 4; d++) {
            int colG = d * 16 + qcol;
            float4 q0 = quad_merge(modd, cc[mf][2 * d][0], cc[mf][2 * d][1],
                                          cc[mf][2 * d + 1][0], cc[mf][2 * d + 1][1]);
            __stcs(reinterpret_cast<float4*>(ctx + (long long)r0 * Dc + colG), q0);
            float4 q1 = quad_merge(modd, cc[mf][2 * d][2], cc[mf][2 * d][3],
                                          cc[mf][2 * d + 1][2], cc[mf][2 * d + 1][3]);
            __stcs(reinterpret_cast<float4*>(ctx + (long long)r1 * Dc + colG), q1);
        }
    }
}

extern "C" void kernel_launch(void* const* d_in, const int* in_sizes, int n_in,
                              void* d_out, int out_size) {
    (void)in_sizes; (void)n_in; (void)out_size;
    const float* q = (const float*)d_in[0];
    const float4* k = (const float4*)d_in[1];
    const float4* v = (const float4*)d_in[2];
    float* out = (float*)d_out;

    cvt_kernel<<<(2 * N4 + 255) / 256, 256>>>(k, v);

    cudaFuncSetAttribute(sdpa_kernel,
                         cudaFuncAttributeMaxDynamicSharedMemorySize, SMEM_TOTAL);
    dim3 grid(Sc / QT, Bc * Hc);  // 8 x 96
    sdpa_kernel<<<grid, NT, SMEM_TOTAL>>>(q, out);
}

// round 17
// speedup vs baseline: 1.4807x; 1.0201x over previous
#include <cuda_runtime.h>
#include <cuda_fp16.h>
#include <cstdint>

// fp16 mma.sync attention — R16 base (2 CTAs/SM, full-tile 16-chain ILP) +
// pass-A exp via ex2.approx.f16x2 (half the MUFU ops) + pass-A KT=128 staging
// (half the barriers). Pass B unchanged: 3-stage (K+V) cp.async, lg2-fold
// normalize, register-resident P, quad_merge STG.128 stores.

namespace {
constexpr int Bc = 8, Hc = 12, Sc = 1024, Dc = 64;
constexpr int QT = 128, KT = 64, NKT = Sc / KT;
constexpr long long SCORE_ELEMS = (long long)Bc * Hc * Sc * Sc;
constexpr float EC = 0.18033688011112042f;  // log2(e) / 8
constexpr int NELEM = Bc * Hc * Sc * Dc;
constexpr int N8 = NELEM / 8;
constexpr int NT = 128;

constexpr int OFF_Q = 0;
constexpr int OFF_ST = 16384;
constexpr int STAGE_SZ = 16384, V_IN_STAGE = 8192;
constexpr int SMEM_TOTAL = OFF_ST + 3 * STAGE_SZ;  // 65536

__device__ __forceinline__ uint32_t swz(uint32_t off) { return off ^ ((off >> 3) & 0x70); }
__device__ __forceinline__ uint32_t smem_u32(const void* p) {
    uint32_t a;
    asm("{ .reg .u64 t; cvta.to.shared.u64 t, %1; cvt.u32.u64 %0, t; }" : "=r"(a) : "l"(p));
    return a;
}
__device__ __forceinline__ uint32_t h2u(__half2 h) { return *reinterpret_cast<uint32_t*>(&h); }
__device__ __forceinline__ float ex2(float x) {
    float r;
    asm("ex2.approx.f32 %0, %1;" : "=f"(r) : "f"(x));
    return r;
}
__device__ __forceinline__ float lg2(float x) {
    float r;
    asm("lg2.approx.f32 %0, %1;" : "=f"(r) : "f"(x));
    return r;
}
__device__ __forceinline__ void ldsm4(uint32_t r[4], uint32_t a) {
    asm volatile("ldmatrix.sync.aligned.m8n8.x4.shared.b16 {%0,%1,%2,%3}, [%4];"
                 : "=r"(r[0]), "=r"(r[1]), "=r"(r[2]), "=r"(r[3]) : "r"(a));
}
__device__ __forceinline__ void ldsm4t(uint32_t r[4], uint32_t a) {
    asm volatile("ldmatrix.sync.aligned.m8n8.x4.trans.shared.b16 {%0,%1,%2,%3}, [%4];"
                 : "=r"(r[0]), "=r"(r[1]), "=r"(r[2]), "=r"(r[3]) : "r"(a));
}
__device__ __forceinline__ void mma16816(float c[4], const uint32_t a[4],
                                         uint32_t b0, uint32_t b1) {
    asm volatile(
        "mma.sync.aligned.m16n8k16.row.col.f32.f16.f16.f32 "
        "{%0,%1,%2,%3}, {%4,%5,%6,%7}, {%8,%9}, {%0,%1,%2,%3};"
        : "+f"(c[0]), "+f"(c[1]), "+f"(c[2]), "+f"(c[3])
        : "r"(a[0]), "r"(a[1]), "r"(a[2]), "r"(a[3]), "r"(b0), "r"(b1));
}
__device__ __forceinline__ void cpa16(uint32_t d, const void* s) {
    asm volatile("cp.async.cg.shared.global [%0], [%1], 16;" :: "r"(d), "l"(s) : "memory");
}
#define CP_COMMIT() asm volatile("cp.async.commit_group;" ::: "memory")
#define CP_WAIT1()  asm volatile("cp.async.wait_group 1;" ::: "memory")

__device__ __forceinline__ float4 quad_merge(bool odd, float e0, float e1,
                                             float o0, float o1) {
    float sx = odd ? e0 : o0, sy = odd ? e1 : o1;
    float rx = __shfl_xor_sync(0xffffffffu, sx, 1);
    float ry = __shfl_xor_sync(0xffffffffu, sy, 1);
    return odd ? make_float4(rx, ry, o0, o1) : make_float4(e0, e1, rx, ry);
}
}  // namespace

__device__ __align__(16) __half g_kh[NELEM];
__device__ __align__(16) __half g_vh[NELEM];

__global__ __launch_bounds__(256)
void cvt_kernel(const float4* __restrict__ k, const float4* __restrict__ v) {
    int i = blockIdx.x * blockDim.x + threadIdx.x;
    const float4* src;
    uint4* dst;
    int j;
    if (i < N8) { src = k; dst = reinterpret_cast<uint4*>(g_kh); j = i; }
    else        { src = v; dst = reinterpret_cast<uint4*>(g_vh); j = i - N8; }
    float4 x = src[2 * j], y = src[2 * j + 1];
    dst[j] = make_uint4(h2u(__floats2half2_rn(x.x, x.y)), h2u(__floats2half2_rn(x.z, x.w)),
                        h2u(__floats2half2_rn(y.x, y.y)), h2u(__floats2half2_rn(y.z, y.w)));
}

namespace {
__device__ __forceinline__ void load_tile64(uint32_t dstBase, const __half* gsrc, int tid) {
    #pragma unroll
    for (int i = 0; i < 4; i++) {
        int c = tid + i * NT;
        int r = c >> 3, ch = c & 7;
        cpa16(dstBase + swz((uint32_t)(r * 128 + ch * 16)), gsrc + r * 64 + ch * 8);
    }
}
__device__ __forceinline__ uint32_t stage_off(int kt) {
    return (uint32_t)(OFF_ST + (kt % 3) * STAGE_SZ);
}
}  // namespace

__global__ __launch_bounds__(NT, 2)
void sdpa_kernel(const float* __restrict__ q, float* __restrict__ out) {
    extern __shared__ char smem[];
    const uint32_t sb = smem_u32(smem);
    const int tid = threadIdx.x, lane = tid & 31, wid = tid >> 5;
    const int g = lane >> 2, m = lane & 3;
    const bool modd = (m & 1) != 0;
    const int qcol = modd ? 2 * m + 6 : 2 * m;
    const int rs = wid * 32;
    const uint32_t xr = (uint32_t)((lane & 7) << 4);

    const int bh = blockIdx.y, qb = blockIdx.x;
    const float* qg   = q + ((long long)bh * Sc + qb * QT) * Dc;
    const __half* kgb = g_kh + (long long)bh * Sc * Dc;
    const __half* vgb = g_vh + (long long)bh * Sc * Dc;
    float* score = out + (long long)bh * Sc * Sc + (long long)(qb * QT) * Sc;
    float* ctx   = out + SCORE_ELEMS + ((long long)bh * Sc + qb * QT) * Dc;

    // ---- prologue: pass-A stages 0,1 (2 K subtiles each); convert Q ----
    load_tile64(sb + stage_off(0),        kgb, tid);
    load_tile64(sb + stage_off(0) + 8192, kgb + (long long)KT * Dc, tid);
    CP_COMMIT();
    load_tile64(sb + stage_off(1),        kgb + (long long)(2 * KT) * Dc, tid);
    load_tile64(sb + stage_off(1) + 8192, kgb + (long long)(3 * KT) * Dc, tid);
    CP_COMMIT();
    #pragma unroll
    for (int i0 = 0; i0 < 16; i0++) {
        int i = tid + i0 * NT;
        int r = i >> 4, c4 = (i & 15) << 2;
        float4 x = *reinterpret_cast<const float4*>(qg + r * Dc + c4);
        *reinterpret_cast<uint2*>(smem + OFF_Q + swz((uint32_t)(r * 128 + c4 * 2))) =
            make_uint2(h2u(__floats2half2_rn(x.x, x.y)), h2u(__floats2half2_rn(x.z, x.w)));
    }
    CP_WAIT1();
    __syncthreads();

    uint32_t qf[4][2][4];
    #pragma unroll
    for (int mf = 0; mf < 2; mf++) {
        uint32_t aq = sb + OFF_Q + (uint32_t)((rs + mf * 16 + (lane & 15)) * 128);
        #pragma unroll
        for (int kk = 0; kk < 4; kk++)
            ldsm4(qf[kk][mf], aq + (((uint32_t)(kk * 32 + ((lane >> 4) * 16))) ^ xr));
    }

    const uint32_t krow = (uint32_t)((((lane >> 4) << 3) + (lane & 7)) * 128);
    const uint32_t vrow = (uint32_t)((lane & 15) * 128);
    const uint32_t vc0 = (uint32_t)((lane >> 4) * 16);
    const uint32_t kfr = (uint32_t)(((lane >> 3) & 1) * 16);
    const __half2 ec2 = __float2half2_rn(EC);

    // ===== pass A: row sums; KT=128 stages (2 subtiles/barrier), h2 exp =====
    float rsum[2][2] = {{0.f, 0.f}, {0.f, 0.f}};
    for (int kt2 = 0; kt2 < NKT / 2; kt2++) {
        CP_WAIT1();
        __syncthreads();
        if (kt2 + 2 < NKT / 2) {
            uint32_t st = sb + stage_off(kt2 + 2) - sb;
            load_tile64(sb + stage_off(kt2 + 2),
                        kgb + (long long)(2 * (kt2 + 2)) * KT * Dc, tid);
            load_tile64(sb + stage_off(kt2 + 2) + 8192,
                        kgb + (long long)(2 * (kt2 + 2) + 1) * KT * Dc, tid);
            (void)st;
        }
        CP_COMMIT();

        #pragma unroll
        for (int sub = 0; sub < 2; sub++) {
            const uint32_t kbase = sb + stage_off(kt2) + (uint32_t)(sub * 8192) + krow;
            float acc[2][8][4];
            #pragma unroll
            for (int mf = 0; mf < 2; mf++)
                #pragma unroll
                for (int nf = 0; nf < 8; nf++)
                    acc[mf][nf][0] = acc[mf][nf][1] = acc[mf][nf][2] = acc[mf][nf][3] = 0.f;
            #pragma unroll
            for (int kk = 0; kk < 4; kk++) {
                uint32_t kb = (((uint32_t)(kk * 32)) + kfr) ^ xr;
                #pragma unroll
                for (int nb = 0; nb < 4; nb++) {
                    uint32_t B[4];
                    ldsm4(B, kbase + (uint32_t)(nb * 2048) + kb);
                    #pragma unroll
                    for (int mf = 0; mf < 2; mf++) {
                        mma16816(acc[mf][2 * nb],     qf[kk][mf], B[0], B[1]);
                        mma16816(acc[mf][2 * nb + 1], qf[kk][mf], B[2], B[3]);
                    }
                }
            }
            // h2 exp: 1 MUFU per 2 values; fold to fp32 every 2 nf
            #pragma unroll
            for (int mf = 0; mf < 2; mf++) {
                #pragma unroll
                for (int nf = 0; nf < 8; nf += 2) {
                    __half2 e0a = h2exp2(__hmul2(
                        __floats2half2_rn(acc[mf][nf][0],     acc[mf][nf][1]),     ec2));
                    __half2 e0b = h2exp2(__hmul2(
                        __floats2half2_rn(acc[mf][nf + 1][0], acc[mf][nf + 1][1]), ec2));
                    float2 f0 = __half22float2(__hadd2(e0a, e0b));
                    rsum[mf][0] += f0.x + f0.y;
                    __half2 e1a = h2exp2(__hmul2(
                        __floats2half2_rn(acc[mf][nf][2],     acc[mf][nf][3]),     ec2));
                    __half2 e1b = h2exp2(__hmul2(
                        __floats2half2_rn(acc[mf][nf + 1][2], acc[mf][nf + 1][3]), ec2));
                    float2 f1 = __half22float2(__hadd2(e1a, e1b));
                    rsum[mf][1] += f1.x + f1.y;
                }
            }
        }
    }

    // ---- transition: issue pass-B stages 0,1 (K+V) while reducing ----
    __syncthreads();
    load_tile64(sb + stage_off(0), kgb, tid);
    load_tile64(sb + stage_off(0) + V_IN_STAGE, vgb, tid);
    CP_COMMIT();
    load_tile64(sb + stage_off(1), kgb + (long long)KT * Dc, tid);
    load_tile64(sb + stage_off(1) + V_IN_STAGE, vgb + (long long)KT * Dc, tid);
    CP_COMMIT();

    float l2i[2][2];
    #pragma unroll
    for (int mf = 0; mf < 2; mf++)
        #pragma unroll
        for (int h = 0; h < 2; h++) {
            float s = rsum[mf][h];
            s += __shfl_xor_sync(0xffffffffu, s, 1);
            s += __shfl_xor_sync(0xffffffffu, s, 2);
            l2i[mf][h] = -lg2(s);
        }

    // ========= pass B (unchanged): full-tile QK -> exp burst -> stores -> PV =========
    float cc[2][8][4];
    #pragma unroll
    for (int mf = 0; mf < 2; mf++)
        #pragma unroll
        for (int nf = 0; nf < 8; nf++)
            cc[mf][nf][0] = cc[mf][nf][1] = cc[mf][nf][2] = cc[mf][nf][3] = 0.f;

    for (int kt = 0; kt < NKT; kt++) {
        CP_WAIT1();
        __syncthreads();
        if (kt + 2 < NKT) {
            load_tile64(sb + stage_off(kt + 2), kgb + (long long)(kt + 2) * KT * Dc, tid);
            load_tile64(sb + stage_off(kt + 2) + V_IN_STAGE,
                        vgb + (long long)(kt + 2) * KT * Dc, tid);
        }
        CP_COMMIT();

        const uint32_t kbase = sb + stage_off(kt) + krow;
        const uint32_t vbase = sb + stage_off(kt) + V_IN_STAGE + vrow;

        float acc[2][8][4];
        #pragma unroll
        for (int mf = 0; mf < 2; mf++)
            #pragma unroll
            for (int nf = 0; nf < 8; nf++)
                acc[mf][nf][0] = acc[mf][nf][1] = acc[mf][nf][2] = acc[mf][nf][3] = 0.f;
        #pragma unroll
        for (int kk = 0; kk < 4; kk++) {
            uint32_t kb = (((uint32_t)(kk * 32)) + kfr) ^ xr;
            #pragma unroll
            for (int nb = 0; nb < 4; nb++) {
                uint32_t B[4];
                ldsm4(B, kbase + (uint32_t)(nb * 2048) + kb);
                #pragma unroll
                for (int mf = 0; mf < 2; mf++) {
                    mma16816(acc[mf][2 * nb],     qf[kk][mf], B[0], B[1]);
                    mma16816(acc[mf][2 * nb + 1], qf[kk][mf], B[2], B[3]);
                }
            }
        }

        #pragma unroll
        for (int mf = 0; mf < 2; mf++)
            #pragma unroll
            for (int nf = 0; nf < 8; nf++) {
                acc[mf][nf][0] = ex2(__fmaf_rn(acc[mf][nf][0], EC, l2i[mf][0]));
                acc[mf][nf][1] = ex2(__fmaf_rn(acc[mf][nf][1], EC, l2i[mf][0]));
                acc[mf][nf][2] = ex2(__fmaf_rn(acc[mf][nf][2], EC, l2i[mf][1]));
                acc[mf][nf][3] = ex2(__fmaf_rn(acc[mf][nf][3], EC, l2i[mf][1]));
            }

        #pragma unroll
        for (int mf = 0; mf < 2; mf++) {
            const int r0 = rs + mf * 16 + g, r1 = r0 + 8;
            #pragma unroll
            for (int c = 0; c < 4; c++) {
                int colG = kt * KT + c * 16 + qcol;
                float4 q0 = quad_merge(modd, acc[mf][2 * c][0], acc[mf][2 * c][1],
                                              acc[mf][2 * c + 1][0], acc[mf][2 * c + 1][1]);
                __stcs(reinterpret_cast<float4*>(score + (long long)r0 * Sc + colG), q0);
                float4 q1 = quad_merge(modd, acc[mf][2 * c][2], acc[mf][2 * c][3],
                                              acc[mf][2 * c + 1][2], acc[mf][2 * c + 1][3]);
                __stcs(reinterpret_cast<float4*>(score + (long long)r1 * Sc + colG), q1);
            }
        }

        #pragma unroll
        for (int c = 0; c < 4; c++) {
            uint32_t pa[2][4];
            #pragma unroll
            for (int mf = 0; mf < 2; mf++) {
                pa[mf][0] = h2u(__floats2half2_rn(acc[mf][2 * c][0],     acc[mf][2 * c][1]));
                pa[mf][1] = h2u(__floats2half2_rn(acc[mf][2 * c][2],     acc[mf][2 * c][3]));
                pa[mf][2] = h2u(__floats2half2_rn(acc[mf][2 * c + 1][0], acc[mf][2 * c + 1][1]));
                pa[mf][3] = h2u(__floats2half2_rn(acc[mf][2 * c + 1][2], acc[mf][2 * c + 1][3]));
            }
            uint32_t vb = vbase + (uint32_t)(c * 2048);
            #pragma unroll
            for (int db = 0; db < 4; db++) {
                uint32_t B[4];
                ldsm4t(B, vb + ((vc0 + (uint32_t)(db * 32)) ^ xr));
                #pragma unroll
                for (int mf = 0; mf < 2; mf++) {
                    mma16816(cc[mf][2 * db],     pa[mf], B[0], B[1]);
                    mma16816(cc[mf][2 * db + 1], pa[mf], B[2], B[3]);
                }
            }
        }
    }

    // ---- write context (coalesced STG.128) ----
    #pragma unroll
    for (int mf = 0; mf < 2; mf++) {
        const int r0 = rs + mf * 16 + g, r1 = r0 + 8;
        #pragma unroll
        for (int d = 0; d < 4; d++) {
            int colG = d * 16 + qcol;
            float4 q0 = quad_merge(modd, cc[mf][2 * d][0], cc[mf][2 * d][1],
                                          cc[mf][2 * d + 1][0], cc[mf][2 * d + 1][1]);
            __stcs(reinterpret_cast<float4*>(ctx + (long long)r0 * Dc + colG), q0);
            float4 q1 = quad_merge(modd, cc[mf][2 * d][2], cc[mf][2 * d][3],
                                          cc[mf][2 * d + 1][2], cc[mf][2 * d + 1][3]);
            __stcs(reinterpret_cast<float4*>(ctx + (long long)r1 * Dc + colG), q1);
        }
    }
}

extern "C" void kernel_launch(void* const* d_in, const int* in_sizes, int n_in,
                              void* d_out, int out_size) {
    (void)in_sizes; (void)n_in; (void)out_size;
    const float* q = (const float*)d_in[0];
    const float4* k = (const float4*)d_in[1];
    const float4* v = (const float4*)d_in[2];
    float* out = (float*)d_out;

    cvt_kernel<<<(2 * N8 + 255) / 256, 256>>>(k, v);

    cudaFuncSetAttribute(sdpa_kernel,
                         cudaFuncAttributeMaxDynamicSharedMemorySize, SMEM_TOTAL);
    dim3 grid(Sc / QT, Bc * Hc);  // 8 x 96
    sdpa_kernel<<<grid, NT, SMEM_TOTAL>>>(q, out);
}